// round 13
// baseline (speedup 1.0000x reference)
#include <cuda_runtime.h>
#include <cstdint>

// Problem constants
#define B 8
#define N 4096
#define C 1024
#define H 16
#define D 64
#define SCALE 0.125f

typedef unsigned long long ull;

// Scratch (no cudaMalloc allowed)
__device__ float g_k[B * C];        // [b][h*D+d]
__device__ float g_v[B * C];
__device__ float g_u[B * H * C];    // [b][h][c]  folded Wq*k
__device__ float g_M[B * H * C];    // [b][h][c]  folded Wp*v
__device__ ull g_attnd[B * N * H];  // duplicated f32x2 sigmoid gates, 4MB

// Packed fp32x2 helpers (sm_103a)
#define FMA2(acc, a, bb) asm("fma.rn.f32x2 %0, %1, %2, %0;" : "+l"(acc) : "l"(a), "l"(bb))
#define ADD2(d, a, bb)   asm("add.rn.f32x2 %0, %1, %2;"     : "=l"(d)   : "l"(a), "l"(bb))

// Volatile loads: ptxas cannot sink these -> guaranteed front-batched MLP.
#define LDGV4(dst, ptr)                                                     \
  asm volatile("ld.global.nc.v4.f32 {%0,%1,%2,%3}, [%4];"                   \
               : "=f"(dst.x), "=f"(dst.y), "=f"(dst.z), "=f"(dst.w)         \
               : "l"(ptr))
#define LDGF(dst, ptr) \
  asm volatile("ld.global.nc.f32 %0, [%1];" : "=f"(dst) : "l"(ptr))

#define CPASYNC16(smem_u32, gptr)                                           \
  asm volatile("cp.async.cg.shared.global [%0], [%1], 16;" ::"r"(smem_u32), \
               "l"(gptr))
#define COMMIT() asm volatile("cp.async.commit_group;" ::: "memory")
#define WAITG(n) asm volatile("cp.async.wait_group %0;" ::"n"(n) : "memory")

// ---------------------------------------------------------------------------
// P1: k = emb @ Wk.T, v = emb @ Wv.T.   (protected win)
// ---------------------------------------------------------------------------
__global__ void __launch_bounds__(128) precompute_kv(
    const float* __restrict__ emb, const float* __restrict__ Wk,
    const float* __restrict__ Wv) {
  int gw = (blockIdx.x * 128 + threadIdx.x) >> 5;  // 0..4095
  int lane = threadIdx.x & 31;
  int sel = gw >> 11;
  int rem = gw & 2047;
  int j = rem >> 1;
  int bh = (rem & 1) * 4;
  const float* W = sel ? Wv : Wk;
  float* dst = sel ? g_v : g_k;
  const float4* w4 = reinterpret_cast<const float4*>(W + j * C);
  const float4* e4 = reinterpret_cast<const float4*>(emb);

  float4 wv[8];
#pragma unroll
  for (int i = 0; i < 8; i++) LDGV4(wv[i], w4 + lane + 32 * i);

  float acc[4];
#pragma unroll
  for (int b = 0; b < 4; b++) acc[b] = 0.f;
#pragma unroll
  for (int b = 0; b < 4; b++) {
    float4 e[8];
#pragma unroll
    for (int i = 0; i < 8; i++) e[i] = e4[(bh + b) * 256 + lane + 32 * i];
#pragma unroll
    for (int i = 0; i < 8; i++)
      acc[b] += wv[i].x * e[i].x + wv[i].y * e[i].y + wv[i].z * e[i].z +
                wv[i].w * e[i].w;
  }
#pragma unroll
  for (int b = 0; b < 4; b++)
    for (int s = 16; s; s >>= 1) acc[b] += __shfl_xor_sync(0xffffffffu, acc[b], s);
  if (lane == 0) {
#pragma unroll
    for (int b = 0; b < 4; b++) dst[(bh + b) * C + j] = acc[b];
  }
}

// ---------------------------------------------------------------------------
// P2: u/M fold.  grid (4,16,2).   (protected)
// ---------------------------------------------------------------------------
__global__ void __launch_bounds__(256) precompute_uM(
    const float* __restrict__ Wq, const float* __restrict__ Wp) {
  __shared__ float kk[4][D];
  __shared__ float vv[4][D];
  int h = blockIdx.y;
  int bg = blockIdx.z * 4;
  int c = blockIdx.x * 256 + threadIdx.x;
  {
    int b = threadIdx.x >> 6, d = threadIdx.x & 63;
    kk[b][d] = g_k[(bg + b) * C + h * D + d];
    vv[b][d] = g_v[(bg + b) * C + h * D + d];
  }
  __syncthreads();

  float acc[4];
#pragma unroll
  for (int b = 0; b < 4; b++) acc[b] = 0.f;
#pragma unroll
  for (int d0 = 0; d0 < D; d0 += 16) {
    float wq[16];
#pragma unroll
    for (int jj = 0; jj < 16; jj++) LDGF(wq[jj], Wq + (h * D + d0 + jj) * C + c);
#pragma unroll
    for (int jj = 0; jj < 16; jj++)
#pragma unroll
      for (int b = 0; b < 4; b++) acc[b] += wq[jj] * kk[b][d0 + jj];
  }
#pragma unroll
  for (int b = 0; b < 4; b++) g_u[((bg + b) * H + h) * C + c] = acc[b];

  float acc2[4];
#pragma unroll
  for (int b = 0; b < 4; b++) acc2[b] = 0.f;
  const float4* wp4 = reinterpret_cast<const float4*>(Wp + c * C + h * D);
#pragma unroll
  for (int i0 = 0; i0 < 16; i0 += 8) {
    float4 wp[8];
#pragma unroll
    for (int i = 0; i < 8; i++) LDGV4(wp[i], wp4 + i0 + i);
#pragma unroll
    for (int i = 0; i < 8; i++) {
      int d = (i0 + i) * 4;
#pragma unroll
      for (int b = 0; b < 4; b++)
        acc2[b] += wp[i].x * vv[b][d] + wp[i].y * vv[b][d + 1] +
                   wp[i].z * vv[b][d + 2] + wp[i].w * vv[b][d + 3];
    }
  }
#pragma unroll
  for (int b = 0; b < 4; b++) g_M[((bg + b) * H + h) * C + c] = acc2[b];
}

// ---------------------------------------------------------------------------
// PASS A: attn = sigmoid(SCALE * fea . u).  288 blocks (36/batch) x 256 thr,
// 2 BLOCKS/SM (smem 109KB).  u[b] resident; fea via 2-slot ring of
// 16-row x 256-col chunks; issue-after-compute; one commit per iteration.
// CSTR = 260 floats (1040B rows, 16B-aligned — R12 crash was CSTR=257
// giving 1028B rows, misaligned for cp.async/LDS.128).
// ---------------------------------------------------------------------------
#define NBLK_A 288
#define BPB_A 36
#define TPB_A 256              // 16-row tiles per batch
#define CSTR 260               // floats per chunk row (256 + 4 pad)
#define CSLOT (16 * CSTR)      // 4160 floats
#define PSTR 20
#define U_FLOATS (H * C)       // 16384
#define SMEM_A ((U_FLOATS + 2 * CSLOT + 8 * 16 * PSTR) * 4)  // 109056 B

__global__ void __launch_bounds__(256, 2) attn_pass(
    const float* __restrict__ fea) {
  extern __shared__ __align__(16) float sm[];
  float* u_s = sm;                    // [h][1024]
  float* ring = sm + U_FLOATS;        // 2 x CSLOT
  float* part = ring + 2 * CSLOT;     // [w8][r16][PSTR]

  const int t = threadIdx.x;
  const int w = t >> 5;
  const int l = t & 31;
  const int row = l & 15;
  const int jh = l >> 4;

  const int batch = blockIdx.x / BPB_A;
  const int bi = blockIdx.x % BPB_A;
  const int ts = batch * TPB_A + (bi * TPB_A) / BPB_A;
  const int te = batch * TPB_A + ((bi + 1) * TPB_A) / BPB_A;
  const int nQ = (te - ts) * 4;

  // chunk q: tile ts+q/4, col chunk q&3, slot q&1.  1024 x16B / 256thr = 4.
#define ISSUE_C(q)                                                          \
  {                                                                         \
    const float* srcb =                                                     \
        fea + (size_t)(ts + (q) / 4) * 16384 + ((q) & 3) * 256;             \
    float* db = ring + ((q) & 1) * CSLOT;                                   \
    _Pragma("unroll") for (int i = 0; i < 4; i++) {                         \
      int idx = t + 256 * i;                                                \
      int r = idx >> 6;                                                     \
      int c4 = idx & 63;                                                    \
      unsigned ds =                                                         \
          (unsigned)__cvta_generic_to_shared(db + r * CSTR + c4 * 4);       \
      CPASYNC16(ds, srcb + r * 1024 + c4 * 4);                              \
    }                                                                       \
  }

  // Prologue: group0 = (u + chunk0), group1 = chunk1.
  {
    const float4* gu4 = reinterpret_cast<const float4*>(g_u + batch * U_FLOATS);
#pragma unroll
    for (int i = 0; i < 16; i++) {
      int idx = t + 256 * i;
      unsigned ds = (unsigned)__cvta_generic_to_shared(u_s + idx * 4);
      CPASYNC16(ds, gu4 + idx);
    }
  }
  ISSUE_C(0); COMMIT();
  ISSUE_C(1); COMMIT();

  ull p2[H];

  for (int q = 0; q < nQ; ++q) {
    WAITG(1);         // groups complete in order -> chunk q (and u) landed
    __syncthreads();

    const int ck = q & 3;
    if (ck == 0) {
#pragma unroll
      for (int h = 0; h < H; h++) p2[h] = 0ull;
    }

    // thread = (row, jh); per-thread f4 cols: w*8 + jh*4 + jj.
    // u is 2-addr broadcast LDS.128; fea conflict-free per 8-lane phase.
    const float* fp = ring + (q & 1) * CSLOT + row * CSTR;
    const float* ub = u_s + ck * 256;
#pragma unroll
    for (int jj = 0; jj < 4; jj++) {
      const int c4 = w * 8 + jh * 4 + jj;
      ulonglong2 f = *reinterpret_cast<const ulonglong2*>(fp + c4 * 4);
#pragma unroll
      for (int h = 0; h < H; h++) {
        ulonglong2 uu =
            *reinterpret_cast<const ulonglong2*>(ub + h * C + c4 * 4);
        FMA2(p2[h], f.x, uu.x);
        FMA2(p2[h], f.y, uu.y);
      }
    }

    if (ck == 3) {  // tile done: fold, cross-jh shuffle, 8-warp reduce
      const int tile = ts + (q >> 2);
      float s[H];
#pragma unroll
      for (int h = 0; h < H; h++) {
        float lo, hi;
        asm("mov.b64 {%0,%1}, %2;" : "=f"(lo), "=f"(hi) : "l"(p2[h]));
        s[h] = lo + hi;
        s[h] += __shfl_xor_sync(0xffffffffu, s[h], 16);
      }
      if (jh == 0) {
        float* pp = part + (w * 16 + row) * PSTR;
#pragma unroll
        for (int h4 = 0; h4 < 4; h4++)
          *reinterpret_cast<float4*>(pp + h4 * 4) = make_float4(
              s[h4 * 4], s[h4 * 4 + 1], s[h4 * 4 + 2], s[h4 * 4 + 3]);
      }
      __syncthreads();
      {
        int r = t >> 4, h = t & 15;
        float sum = 0.f;
#pragma unroll
        for (int ww = 0; ww < 8; ww++) sum += part[(ww * 16 + r) * PSTR + h];
        float a = 1.f / (1.f + __expf(-sum * SCALE));
        ull ad;
        asm("mov.b64 %0, {%1,%1};" : "=l"(ad) : "f"(a));
        g_attnd[(tile * 16 + r) * H + h] = ad;
      }
    }

    __syncthreads();  // all reads of slot q&1 done before refill below
    if (q + 2 < nQ) { ISSUE_C(q + 2); }
    COMMIT();  // exactly one commit per iteration (possibly empty)
  }
}

// ---------------------------------------------------------------------------
// PASS B: out = fea + bp + attn @ M.  512 blocks x 256 thr, 2 BLOCKS/SM.
// Block = 64 rows; thread = 4 cols; M[b] slice in 64 regs; fea via 3-slot
// cp.async ring of 8-row groups (64-128KB in flight per SM).
// ---------------------------------------------------------------------------
#define GSLOT (8 * 1024)                     // floats per group slot
#define SMEM_B (64 * H * 8 + 3 * GSLOT * 4)  // 8192 + 98304 = 106496 B

__global__ void __launch_bounds__(256, 2) out_pass(
    const float* __restrict__ fea, const float* __restrict__ bp,
    float* __restrict__ out) {
  extern __shared__ __align__(16) float smb[];
  ull* attn_s = reinterpret_cast<ull*>(smb);   // 64 x 16 ull (8KB)
  float* ring = smb + 64 * H * 2;              // 3 x GSLOT

  const int t = threadIdx.x;
  const size_t row0 = (size_t)blockIdx.x * 64;
  const int b = (int)(row0 >> 12);
  const int c0 = t * 4;

  // stage attn for the block's 64 rows (1024 ull = 512 ulonglong2)
  {
    const ulonglong2* src =
        reinterpret_cast<const ulonglong2*>(g_attnd + row0 * H);
    ulonglong2* dst = reinterpret_cast<ulonglong2*>(attn_s);
#pragma unroll
    for (int i = 0; i < 2; i++) dst[t + 256 * i] = src[t + 256 * i];
  }

  ulonglong2 bpv = *reinterpret_cast<const ulonglong2*>(bp + c0);
  ulonglong2 M2[H];
#pragma unroll
  for (int h = 0; h < H; h++)
    M2[h] = *reinterpret_cast<const ulonglong2*>(g_M + (b * H + h) * C + c0);

  // group grp: rows [row0+grp*8, +8), slot grp%3.  2048 x16B / 256 = 8 each.
#define ISSUE_B(grp)                                                        \
  {                                                                         \
    const float* srcb = fea + (row0 + (grp) * 8) * (size_t)1024;            \
    float* db = ring + ((grp) % 3) * GSLOT;                                 \
    _Pragma("unroll") for (int i = 0; i < 8; i++) {                         \
      int idx = t + 256 * i;                                                \
      int r = idx >> 8;                                                     \
      int c4 = idx & 255;                                                   \
      unsigned ds =                                                         \
          (unsigned)__cvta_generic_to_shared(db + r * 1024 + c4 * 4);       \
      CPASYNC16(ds, srcb + r * 1024 + c4 * 4);                              \
    }                                                                       \
  }

  ISSUE_B(0); COMMIT();
  ISSUE_B(1); COMMIT();

  for (int grp = 0; grp < 8; ++grp) {
    WAITG(1);         // group grp landed (in-order completion)
    __syncthreads();  // visibility; compute(grp-1) done -> slot (grp+2)%3 free
    if (grp + 2 < 8) { ISSUE_B(grp + 2); }
    COMMIT();         // one commit per iteration (possibly empty)

    const float* fb = ring + (grp % 3) * GSLOT;
    float* ob = out + (row0 + grp * 8) * (size_t)1024 + c0;
#pragma unroll
    for (int r = 0; r < 8; r++) {
      ulonglong2 f = *reinterpret_cast<const ulonglong2*>(fb + r * 1024 + c0);
      ull oa, oc;
      ADD2(oa, f.x, bpv.x);
      ADD2(oc, f.y, bpv.y);
      const ull* ar = attn_s + (grp * 8 + r) * H;
#pragma unroll
      for (int hg = 0; hg < 8; hg++) {
        ulonglong2 a2 = *reinterpret_cast<const ulonglong2*>(ar + hg * 2);
        FMA2(oa, a2.x, M2[hg * 2].x);
        FMA2(oc, a2.x, M2[hg * 2].y);
        FMA2(oa, a2.y, M2[hg * 2 + 1].x);
        FMA2(oc, a2.y, M2[hg * 2 + 1].y);
      }
      ulonglong2 o;
      o.x = oa;
      o.y = oc;
      *reinterpret_cast<ulonglong2*>(ob + r * 1024) = o;
    }
  }
}

// ---------------------------------------------------------------------------
extern "C" void kernel_launch(void* const* d_in, const int* in_sizes, int n_in,
                              void* d_out, int out_size) {
  const float* fea = (const float*)d_in[0];
  const float* emb = (const float*)d_in[1];
  const float* Wq  = (const float*)d_in[2];
  const float* Wk  = (const float*)d_in[3];
  const float* Wv  = (const float*)d_in[4];
  const float* Wp  = (const float*)d_in[5];
  const float* bp  = (const float*)d_in[6];
  float* out = (float*)d_out;

  cudaFuncSetAttribute(attn_pass, cudaFuncAttributeMaxDynamicSharedMemorySize,
                       SMEM_A);
  cudaFuncSetAttribute(out_pass, cudaFuncAttributeMaxDynamicSharedMemorySize,
                       SMEM_B);

  precompute_kv<<<1024, 128>>>(emb, Wk, Wv);
  precompute_uM<<<dim3(4, H, 2), 256>>>(Wq, Wp);
  attn_pass<<<NBLK_A, 256, SMEM_A>>>(fea);
  out_pass<<<512, 256, SMEM_B>>>(fea, bp, out);
}

// round 14
// speedup vs baseline: 1.0599x; 1.0599x over previous
#include <cuda_runtime.h>
#include <cstdint>

// Problem constants
#define B 8
#define N 4096
#define C 1024
#define H 16
#define D 64
#define SCALE 0.125f

typedef unsigned long long ull;

// Scratch (no cudaMalloc allowed)
__device__ float g_k[B * C];        // [b][h*D+d]
__device__ float g_v[B * C];
__device__ float g_u[B * H * C];    // [b][h][c]  folded Wq*k
__device__ float g_M[B * H * C];    // [b][h][c]  folded Wp*v
__device__ ull g_attnd[B * N * H];  // duplicated f32x2 sigmoid gates, 4MB

// Packed fp32x2 helpers (sm_103a)
#define FMA2(acc, a, bb) asm("fma.rn.f32x2 %0, %1, %2, %0;" : "+l"(acc) : "l"(a), "l"(bb))
#define ADD2(d, a, bb)   asm("add.rn.f32x2 %0, %1, %2;"     : "=l"(d)   : "l"(a), "l"(bb))

// Volatile loads: ptxas cannot sink these -> guaranteed front-batched MLP.
#define LDGV4(dst, ptr)                                                     \
  asm volatile("ld.global.nc.v4.f32 {%0,%1,%2,%3}, [%4];"                   \
               : "=f"(dst.x), "=f"(dst.y), "=f"(dst.z), "=f"(dst.w)         \
               : "l"(ptr))
#define LDGF(dst, ptr) \
  asm volatile("ld.global.nc.f32 %0, [%1];" : "=f"(dst) : "l"(ptr))

#define CPASYNC16(smem_u32, gptr)                                           \
  asm volatile("cp.async.cg.shared.global [%0], [%1], 16;" ::"r"(smem_u32), \
               "l"(gptr))
#define COMMIT() asm volatile("cp.async.commit_group;" ::: "memory")
#define WAITG(n) asm volatile("cp.async.wait_group %0;" ::"n"(n) : "memory")

__device__ __forceinline__ ull shfl_xor_u64(ull x, int m) {
  unsigned lo = (unsigned)x, hi = (unsigned)(x >> 32);
  lo = __shfl_xor_sync(0xffffffffu, lo, m);
  hi = __shfl_xor_sync(0xffffffffu, hi, m);
  return ((ull)hi << 32) | lo;
}

// ---------------------------------------------------------------------------
// P1: k = emb @ Wk.T, v = emb @ Wv.T.   (protected win)
// ---------------------------------------------------------------------------
__global__ void __launch_bounds__(128) precompute_kv(
    const float* __restrict__ emb, const float* __restrict__ Wk,
    const float* __restrict__ Wv) {
  int gw = (blockIdx.x * 128 + threadIdx.x) >> 5;  // 0..4095
  int lane = threadIdx.x & 31;
  int sel = gw >> 11;
  int rem = gw & 2047;
  int j = rem >> 1;
  int bh = (rem & 1) * 4;
  const float* W = sel ? Wv : Wk;
  float* dst = sel ? g_v : g_k;
  const float4* w4 = reinterpret_cast<const float4*>(W + j * C);
  const float4* e4 = reinterpret_cast<const float4*>(emb);

  float4 wv[8];
#pragma unroll
  for (int i = 0; i < 8; i++) LDGV4(wv[i], w4 + lane + 32 * i);

  float acc[4];
#pragma unroll
  for (int b = 0; b < 4; b++) acc[b] = 0.f;
#pragma unroll
  for (int b = 0; b < 4; b++) {
    float4 e[8];
#pragma unroll
    for (int i = 0; i < 8; i++) e[i] = e4[(bh + b) * 256 + lane + 32 * i];
#pragma unroll
    for (int i = 0; i < 8; i++)
      acc[b] += wv[i].x * e[i].x + wv[i].y * e[i].y + wv[i].z * e[i].z +
                wv[i].w * e[i].w;
  }
#pragma unroll
  for (int b = 0; b < 4; b++)
    for (int s = 16; s; s >>= 1) acc[b] += __shfl_xor_sync(0xffffffffu, acc[b], s);
  if (lane == 0) {
#pragma unroll
    for (int b = 0; b < 4; b++) dst[(bh + b) * C + j] = acc[b];
  }
}

// ---------------------------------------------------------------------------
// P2: u/M fold.  grid (4,16,2).   (protected)
// ---------------------------------------------------------------------------
__global__ void __launch_bounds__(256) precompute_uM(
    const float* __restrict__ Wq, const float* __restrict__ Wp) {
  __shared__ float kk[4][D];
  __shared__ float vv[4][D];
  int h = blockIdx.y;
  int bg = blockIdx.z * 4;
  int c = blockIdx.x * 256 + threadIdx.x;
  {
    int b = threadIdx.x >> 6, d = threadIdx.x & 63;
    kk[b][d] = g_k[(bg + b) * C + h * D + d];
    vv[b][d] = g_v[(bg + b) * C + h * D + d];
  }
  __syncthreads();

  float acc[4];
#pragma unroll
  for (int b = 0; b < 4; b++) acc[b] = 0.f;
#pragma unroll
  for (int d0 = 0; d0 < D; d0 += 16) {
    float wq[16];
#pragma unroll
    for (int jj = 0; jj < 16; jj++) LDGF(wq[jj], Wq + (h * D + d0 + jj) * C + c);
#pragma unroll
    for (int jj = 0; jj < 16; jj++)
#pragma unroll
      for (int b = 0; b < 4; b++) acc[b] += wq[jj] * kk[b][d0 + jj];
  }
#pragma unroll
  for (int b = 0; b < 4; b++) g_u[((bg + b) * H + h) * C + c] = acc[b];

  float acc2[4];
#pragma unroll
  for (int b = 0; b < 4; b++) acc2[b] = 0.f;
  const float4* wp4 = reinterpret_cast<const float4*>(Wp + c * C + h * D);
#pragma unroll
  for (int i0 = 0; i0 < 16; i0 += 8) {
    float4 wp[8];
#pragma unroll
    for (int i = 0; i < 8; i++) LDGV4(wp[i], wp4 + i0 + i);
#pragma unroll
    for (int i = 0; i < 8; i++) {
      int d = (i0 + i) * 4;
#pragma unroll
      for (int b = 0; b < 4; b++)
        acc2[b] += wp[i].x * vv[b][d] + wp[i].y * vv[b][d + 1] +
                   wp[i].z * vv[b][d + 2] + wp[i].w * vv[b][d + 3];
    }
  }
#pragma unroll
  for (int b = 0; b < 4; b++) g_M[((bg + b) * H + h) * C + c] = acc2[b];
}

// ---------------------------------------------------------------------------
// PASS A: attn = sigmoid(SCALE * fea . u).  288 blocks (36/batch) x 256 thr,
// 2 blocks/SM (smem 96.5KB).  R13 was smem-crossbar bound (17 LDS.128 per
// 32 FMA2).  New mapping: warp = (rowgroup w&3, headhalf w>>2), lane =
// f4-column; thread accumulates a 4-row x 8-head block (32 packed accums,
// 64 regs) -> 12 LDS.128 per 64 FMA2 (2.8x less smem traffic).  Tile
// reduction = in-warp 32-value ull butterfly (no smem partials).
// ---------------------------------------------------------------------------
#define NBLK_A 288
#define BPB_A 36
#define TPB_A 256              // 16-row tiles per batch
#define CSTR 260               // floats per chunk row (256 + 4 pad, 16B mult)
#define CSLOT (16 * CSTR)      // 4160 floats
#define U_FLOATS (H * C)       // 16384
#define SMEM_A ((U_FLOATS + 2 * CSLOT) * 4)  // 98816 B

__global__ void __launch_bounds__(256, 2) attn_pass(
    const float* __restrict__ fea) {
  extern __shared__ __align__(16) float sm[];
  float* u_s = sm;                    // [h][1024]
  float* ring = sm + U_FLOATS;        // 2 x CSLOT

  const int t = threadIdx.x;
  const int w = t >> 5;
  const int l = t & 31;
  const int rg = w & 3;   // rowgroup: rows rg*4 .. rg*4+3
  const int hh = w >> 2;  // headhalf: heads hh*8 .. hh*8+7

  const int batch = blockIdx.x / BPB_A;
  const int bi = blockIdx.x % BPB_A;
  const int ts = batch * TPB_A + (bi * TPB_A) / BPB_A;
  const int te = batch * TPB_A + ((bi + 1) * TPB_A) / BPB_A;
  const int nQ = (te - ts) * 4;

  // chunk q: tile ts+q/4, col chunk q&3, slot q&1.  1024 x16B / 256thr = 4.
#define ISSUE_C(q)                                                          \
  {                                                                         \
    const float* srcb =                                                     \
        fea + (size_t)(ts + (q) / 4) * 16384 + ((q) & 3) * 256;             \
    float* db = ring + ((q) & 1) * CSLOT;                                   \
    _Pragma("unroll") for (int i = 0; i < 4; i++) {                         \
      int idx = t + 256 * i;                                                \
      int r = idx >> 6;                                                     \
      int c4 = idx & 63;                                                    \
      unsigned ds =                                                         \
          (unsigned)__cvta_generic_to_shared(db + r * CSTR + c4 * 4);       \
      CPASYNC16(ds, srcb + r * 1024 + c4 * 4);                              \
    }                                                                       \
  }

  // Prologue: group0 = (u + chunk0), group1 = chunk1.
  {
    const float4* gu4 = reinterpret_cast<const float4*>(g_u + batch * U_FLOATS);
#pragma unroll
    for (int i = 0; i < 16; i++) {
      int idx = t + 256 * i;
      unsigned ds = (unsigned)__cvta_generic_to_shared(u_s + idx * 4);
      CPASYNC16(ds, gu4 + idx);
    }
  }
  ISSUE_C(0); COMMIT();
  ISSUE_C(1); COMMIT();

  ull acc[32];  // [r][h]: packed f32x2 partial over this lane's columns

  for (int q = 0; q < nQ; ++q) {
    WAITG(1);         // chunk q (and for q==0, u) landed
    __syncthreads();

    const int ck = q & 3;
    if (ck == 0) {
#pragma unroll
      for (int i = 0; i < 32; i++) acc[i] = 0ull;
    }

    const float* base = ring + (q & 1) * CSLOT;
    const float* ub = u_s + ck * 256;
#pragma unroll
    for (int cc = 0; cc < 2; cc++) {
      const int c4 = cc * 32 + l;
      ulonglong2 f[4];
#pragma unroll
      for (int r = 0; r < 4; r++)
        f[r] = *reinterpret_cast<const ulonglong2*>(
            base + (rg * 4 + r) * CSTR + c4 * 4);
#pragma unroll
      for (int hg = 0; hg < 2; hg++) {
        ulonglong2 uu[4];
#pragma unroll
        for (int j = 0; j < 4; j++)
          uu[j] = *reinterpret_cast<const ulonglong2*>(
              ub + (hh * 8 + hg * 4 + j) * C + c4 * 4);
#pragma unroll
        for (int r = 0; r < 4; r++)
#pragma unroll
          for (int j = 0; j < 4; j++) {
            FMA2(acc[r * 8 + hg * 4 + j], f[r].x, uu[j].x);
            FMA2(acc[r * 8 + hg * 4 + j], f[r].y, uu[j].y);
          }
      }
    }

    if (ck == 3) {  // tile done: 32-value butterfly reduce over 32 lanes.
                    // After level mask m, lanes with (l&m) keep the upper
                    // half; final: lane l holds (r = l>>3, h = l&7).
#define BFLY(m)                                                             \
  _Pragma("unroll") for (int i = 0; i < (m); i++) {                         \
    ull send = (l & (m)) ? acc[i] : acc[i + (m)];                           \
    ull recv = shfl_xor_u64(send, (m));                                     \
    ull keep = (l & (m)) ? acc[i + (m)] : acc[i];                           \
    ADD2(acc[i], keep, recv);                                               \
  }
      BFLY(16) BFLY(8) BFLY(4) BFLY(2) BFLY(1)
#undef BFLY
      float lo, hi;
      asm("mov.b64 {%0,%1}, %2;" : "=f"(lo), "=f"(hi) : "l"(acc[0]));
      float a = 1.f / (1.f + __expf(-(lo + hi) * SCALE));
      ull ad;
      asm("mov.b64 %0, {%1,%1};" : "=l"(ad) : "f"(a));
      const int tile = ts + (q >> 2);
      const int grow = tile * 16 + rg * 4 + (l >> 3);
      g_attnd[grow * H + hh * 8 + (l & 7)] = ad;
    }

    __syncthreads();  // all reads of slot q&1 done before refill below
    if (q + 2 < nQ) { ISSUE_C(q + 2); }
    COMMIT();  // exactly one commit per iteration (possibly empty)
  }
}

// ---------------------------------------------------------------------------
// PASS B: out = fea + bp + attn @ M.  512 blocks x 256 thr, 2 BLOCKS/SM.
// Block = 64 rows; thread = 4 cols; M[b] slice in 64 regs; fea via 3-slot
// cp.async ring of 8-row groups.   (unchanged from R13 — measured 49.3us)
// ---------------------------------------------------------------------------
#define GSLOT (8 * 1024)                     // floats per group slot
#define SMEM_B (64 * H * 8 + 3 * GSLOT * 4)  // 8192 + 98304 = 106496 B

__global__ void __launch_bounds__(256, 2) out_pass(
    const float* __restrict__ fea, const float* __restrict__ bp,
    float* __restrict__ out) {
  extern __shared__ __align__(16) float smb[];
  ull* attn_s = reinterpret_cast<ull*>(smb);   // 64 x 16 ull (8KB)
  float* ring = smb + 64 * H * 2;              // 3 x GSLOT

  const int t = threadIdx.x;
  const size_t row0 = (size_t)blockIdx.x * 64;
  const int b = (int)(row0 >> 12);
  const int c0 = t * 4;

  // stage attn for the block's 64 rows (1024 ull = 512 ulonglong2)
  {
    const ulonglong2* src =
        reinterpret_cast<const ulonglong2*>(g_attnd + row0 * H);
    ulonglong2* dst = reinterpret_cast<ulonglong2*>(attn_s);
#pragma unroll
    for (int i = 0; i < 2; i++) dst[t + 256 * i] = src[t + 256 * i];
  }

  ulonglong2 bpv = *reinterpret_cast<const ulonglong2*>(bp + c0);
  ulonglong2 M2[H];
#pragma unroll
  for (int h = 0; h < H; h++)
    M2[h] = *reinterpret_cast<const ulonglong2*>(g_M + (b * H + h) * C + c0);

  // group grp: rows [row0+grp*8, +8), slot grp%3.  2048 x16B / 256 = 8 each.
#define ISSUE_B(grp)                                                        \
  {                                                                         \
    const float* srcb = fea + (row0 + (grp) * 8) * (size_t)1024;            \
    float* db = ring + ((grp) % 3) * GSLOT;                                 \
    _Pragma("unroll") for (int i = 0; i < 8; i++) {                         \
      int idx = t + 256 * i;                                                \
      int r = idx >> 8;                                                     \
      int c4 = idx & 255;                                                   \
      unsigned ds =                                                         \
          (unsigned)__cvta_generic_to_shared(db + r * 1024 + c4 * 4);       \
      CPASYNC16(ds, srcb + r * 1024 + c4 * 4);                              \
    }                                                                       \
  }

  ISSUE_B(0); COMMIT();
  ISSUE_B(1); COMMIT();

  for (int grp = 0; grp < 8; ++grp) {
    WAITG(1);         // group grp landed (in-order completion)
    __syncthreads();  // visibility; compute(grp-1) done -> slot (grp+2)%3 free
    if (grp + 2 < 8) { ISSUE_B(grp + 2); }
    COMMIT();         // one commit per iteration (possibly empty)

    const float* fb = ring + (grp % 3) * GSLOT;
    float* ob = out + (row0 + grp * 8) * (size_t)1024 + c0;
#pragma unroll
    for (int r = 0; r < 8; r++) {
      ulonglong2 f = *reinterpret_cast<const ulonglong2*>(fb + r * 1024 + c0);
      ull oa, oc;
      ADD2(oa, f.x, bpv.x);
      ADD2(oc, f.y, bpv.y);
      const ull* ar = attn_s + (grp * 8 + r) * H;
#pragma unroll
      for (int hg = 0; hg < 8; hg++) {
        ulonglong2 a2 = *reinterpret_cast<const ulonglong2*>(ar + hg * 2);
        FMA2(oa, a2.x, M2[hg * 2].x);
        FMA2(oc, a2.x, M2[hg * 2].y);
        FMA2(oa, a2.y, M2[hg * 2 + 1].x);
        FMA2(oc, a2.y, M2[hg * 2 + 1].y);
      }
      ulonglong2 o;
      o.x = oa;
      o.y = oc;
      *reinterpret_cast<ulonglong2*>(ob + r * 1024) = o;
    }
  }
}

// ---------------------------------------------------------------------------
extern "C" void kernel_launch(void* const* d_in, const int* in_sizes, int n_in,
                              void* d_out, int out_size) {
  const float* fea = (const float*)d_in[0];
  const float* emb = (const float*)d_in[1];
  const float* Wq  = (const float*)d_in[2];
  const float* Wk  = (const float*)d_in[3];
  const float* Wv  = (const float*)d_in[4];
  const float* Wp  = (const float*)d_in[5];
  const float* bp  = (const float*)d_in[6];
  float* out = (float*)d_out;

  cudaFuncSetAttribute(attn_pass, cudaFuncAttributeMaxDynamicSharedMemorySize,
                       SMEM_A);
  cudaFuncSetAttribute(out_pass, cudaFuncAttributeMaxDynamicSharedMemorySize,
                       SMEM_B);

  precompute_kv<<<1024, 128>>>(emb, Wk, Wv);
  precompute_uM<<<dim3(4, H, 2), 256>>>(Wq, Wp);
  attn_pass<<<NBLK_A, 256, SMEM_A>>>(fea);
  out_pass<<<512, 256, SMEM_B>>>(fea, bp, out);
}